// round 8
// baseline (speedup 1.0000x reference)
#include <cuda_runtime.h>
#include <cuda_bf16.h>
#include <math.h>

typedef unsigned long long ull;

#define NBLK 128
#define NSTEP 50
#define LDP_OUT 50304   // 393*128, padded ld for partials
#define NOUT 50257
#define SPLITK_OUT 4
#define SPLITK_IN 8

// ---------------- device scratch (no allocs allowed) ----------------
__device__ float g_X[64 * 1024];          // padded inputs (rows 50..63 zero)
__device__ float g_Gin[50 * 4096];        // W_ih @ x_t + b_ih + b_hh
__device__ float g_HS[64 * 1024];         // h_t history (rows 50..63 zero)
__device__ float g_h[2][1024];            // double-buffered hidden state
__device__ unsigned g_arrive;             // cumulative grid-barrier counter
__device__ float g_P[SPLITK_OUT * 64 * LDP_OUT];  // split-K partials (reused)

// ---------------- helpers ----------------
__device__ __forceinline__ ull pack2(float x, float y) {
    ull r;
    asm("mov.b64 %0, {%1, %2};" : "=l"(r) : "f"(x), "f"(y));
    return r;
}
__device__ __forceinline__ void ffma2(ull& d, ull a, ull b) {
    asm("fma.rn.f32x2 %0, %1, %2, %0;" : "+l"(d) : "l"(a), "l"(b));
}
__device__ __forceinline__ float sum2(ull a) {
    float2 v = *(float2*)&a;
    return v.x + v.y;
}
__device__ __forceinline__ void red_release_add1(unsigned* p) {
    asm volatile("red.release.gpu.global.add.u32 [%0], 1;" :: "l"(p) : "memory");
}
__device__ __forceinline__ unsigned ld_acquire(const unsigned* p) {
    unsigned v;
    asm volatile("ld.acquire.gpu.global.u32 %0, [%1];" : "=r"(v) : "l"(p) : "memory");
    return v;
}

// ---------------- prep: gather X rows, zero pads, init state, reset barrier ----------------
__global__ void prep_kernel(const int* __restrict__ sent,
                            const float* __restrict__ emb,
                            const float* __restrict__ h0) {
    int b = blockIdx.x;
    int tid = threadIdx.x;  // 256 threads, float4 each -> 1024 floats
    if (b < 64) {
        float4* dst = (float4*)(g_X + b * 1024);
        if (b < 50) {
            int row = (b == 0) ? 1 : sent[b - 1];  // START_ID = 1
            const float4* src = (const float4*)(emb + (size_t)row * 1024);
            dst[tid] = src[tid];
        } else {
            float4 z = make_float4(0.f, 0.f, 0.f, 0.f);
            dst[tid] = z;
            ((float4*)(g_HS + b * 1024))[tid] = z;  // keep GEMM pad rows zero
        }
    } else {
        ((float4*)g_h[0])[tid] = ((const float4*)h0)[tid];
        if (tid == 0) g_arrive = 0u;
    }
}

// ---------------- split-K GEMM with register-pipelined inner loop ----------------
// P[ks][m][n] = A[m][kbeg:kend] . W[n][kbeg:kend]
// BM=64, BN=128, BK=16, 128 threads, 8x8 thread tiles, f32x2.
// smem double-buffered across tiles; operands double-buffered in registers
// within a tile (explicit software pipeline to hide LDS latency).
__global__ __launch_bounds__(128, 4) void gemm_splitk(
    const float* __restrict__ A, const float* __restrict__ W,
    float* __restrict__ P, int N, int K, int ldp, int nsplit) {
    __shared__ ull sAd[2][16][64];     // A duplicated as (a,a) pairs
    __shared__ float sB[2][16][128];

    const int tid = threadIdx.x;
    const int tn = tid & 15;   // n0 = tn*8
    const int tm = tid >> 4;   // m0 = tm*8
    const int n_block = blockIdx.x * 128;
    const int klen = K / nsplit;
    const int kbeg = blockIdx.y * klen;
    const int nk = klen / 16;
    float* Pp = P + (size_t)blockIdx.y * 64 * ldp;

    ull acc[8][4];
#pragma unroll
    for (int i = 0; i < 8; i++)
#pragma unroll
        for (int p = 0; p < 4; p++) acc[i][p] = 0ULL;

    const int mA = tid & 63;
    const int kgA = tid >> 6;
    const int nB = tid & 127;

    float4 ra[2], rb[4];
#pragma unroll
    for (int s = 0; s < 2; s++) {
        int kg = kgA + s * 2;
        ra[s] = *(const float4*)(A + (size_t)mA * K + kbeg + kg * 4);
    }
#pragma unroll
    for (int s = 0; s < 4; s++) {
        int gn = n_block + nB;
        rb[s] = make_float4(0.f, 0.f, 0.f, 0.f);
        if (gn < N) rb[s] = *(const float4*)(W + (size_t)gn * K + kbeg + s * 4);
    }
    {
#pragma unroll
        for (int s = 0; s < 2; s++) {
            int kg = kgA + s * 2;
            sAd[0][kg * 4 + 0][mA] = pack2(ra[s].x, ra[s].x);
            sAd[0][kg * 4 + 1][mA] = pack2(ra[s].y, ra[s].y);
            sAd[0][kg * 4 + 2][mA] = pack2(ra[s].z, ra[s].z);
            sAd[0][kg * 4 + 3][mA] = pack2(ra[s].w, ra[s].w);
        }
#pragma unroll
        for (int s = 0; s < 4; s++) {
            sB[0][s * 4 + 0][nB] = rb[s].x;
            sB[0][s * 4 + 1][nB] = rb[s].y;
            sB[0][s * 4 + 2][nB] = rb[s].z;
            sB[0][s * 4 + 3][nB] = rb[s].w;
        }
    }
    __syncthreads();

    for (int kt = 0; kt < nk; kt++) {
        const int buf = kt & 1;
        // global prefetch of next tile (hidden under this tile's FMAs)
        if (kt + 1 < nk) {
            int kp = kbeg + (kt + 1) * 16;
#pragma unroll
            for (int s = 0; s < 2; s++) {
                int kg = kgA + s * 2;
                ra[s] = *(const float4*)(A + (size_t)mA * K + kp + kg * 4);
            }
#pragma unroll
            for (int s = 0; s < 4; s++) {
                int gn = n_block + nB;
                rb[s] = make_float4(0.f, 0.f, 0.f, 0.f);
                if (gn < N) rb[s] = *(const float4*)(W + (size_t)gn * K + kp + s * 4);
            }
        }
        // register-pipelined smem consumption
        {
            const ull* ab = &sAd[buf][0][tm * 8];
            const ull* bb = (const ull*)&sB[buf][0][tn * 8];
            ull ca[8], cb[4], na[8], nb2[4];
#pragma unroll
            for (int i = 0; i < 8; i++) ca[i] = ab[i];
#pragma unroll
            for (int p = 0; p < 4; p++) cb[p] = bb[p];
#pragma unroll
            for (int k = 0; k < 16; k++) {
                if (k < 15) {
                    const ull* an = ab + (k + 1) * 64;
                    const ull* bn = bb + (k + 1) * 64;
#pragma unroll
                    for (int i = 0; i < 8; i++) na[i] = an[i];
#pragma unroll
                    for (int p = 0; p < 4; p++) nb2[p] = bn[p];
                }
#pragma unroll
                for (int i = 0; i < 8; i++) {
                    ull ai = ca[i];
                    ffma2(acc[i][0], ai, cb[0]);
                    ffma2(acc[i][1], ai, cb[1]);
                    ffma2(acc[i][2], ai, cb[2]);
                    ffma2(acc[i][3], ai, cb[3]);
                }
                if (k < 15) {
#pragma unroll
                    for (int i = 0; i < 8; i++) ca[i] = na[i];
#pragma unroll
                    for (int p = 0; p < 4; p++) cb[p] = nb2[p];
                }
            }
        }
        // store next tile to other smem buffer
        if (kt + 1 < nk) {
            const int nb = buf ^ 1;
#pragma unroll
            for (int s = 0; s < 2; s++) {
                int kg = kgA + s * 2;
                sAd[nb][kg * 4 + 0][mA] = pack2(ra[s].x, ra[s].x);
                sAd[nb][kg * 4 + 1][mA] = pack2(ra[s].y, ra[s].y);
                sAd[nb][kg * 4 + 2][mA] = pack2(ra[s].z, ra[s].z);
                sAd[nb][kg * 4 + 3][mA] = pack2(ra[s].w, ra[s].w);
            }
#pragma unroll
            for (int s = 0; s < 4; s++) {
                sB[nb][s * 4 + 0][nB] = rb[s].x;
                sB[nb][s * 4 + 1][nB] = rb[s].y;
                sB[nb][s * 4 + 2][nB] = rb[s].z;
                sB[nb][s * 4 + 3][nB] = rb[s].w;
            }
            __syncthreads();
        }
    }

#pragma unroll
    for (int i = 0; i < 8; i++) {
        int m = tm * 8 + i;
        float4* dst = (float4*)(Pp + (size_t)m * ldp + n_block + tn * 8);
        dst[0] = *(float4*)&acc[i][0];
        dst[1] = *(float4*)&acc[i][2];
    }
}

// ---------------- combine: out = sum(P[0..3]) + bias ----------------
__global__ void combine_out_kernel(const float* __restrict__ bout,
                                   float* __restrict__ out) {
    int m = blockIdx.y;
    int n = blockIdx.x * 256 + threadIdx.x;
    if (n < NOUT) {
        size_t po = (size_t)m * LDP_OUT + n;
        float s = bout[n];
#pragma unroll
        for (int sp = 0; sp < SPLITK_OUT; sp++)
            s += g_P[(size_t)sp * 64 * LDP_OUT + po];
        out[(size_t)m * NOUT + n] = s;
    }
}

// ---------------- combine: Gin = sum(P[0..7]) + bih + bhh ----------------
__global__ void combine_gin_kernel(const float* __restrict__ bih,
                                   const float* __restrict__ bhh) {
    int m = blockIdx.y;
    int n = blockIdx.x * 256 + threadIdx.x;
    float s = bih[n] + bhh[n];
#pragma unroll
    for (int sp = 0; sp < SPLITK_IN; sp++)
        s += g_P[(size_t)sp * 64 * 4096 + (size_t)m * 4096 + n];
    g_Gin[(size_t)m * 4096 + n] = s;
}

// ---------------- persistent LSTM (warp-per-unit gates + counter barrier) ----------------
// 128 blocks x 256 threads (1/SM). Warp w of block b owns hidden unit u=b*8+w:
// all 4 gate rows; lane = r*8+c (r=gate 0..3, c=chunk 0..7).
// After the 8-lane chunk reduce, the 4 gate sums are gathered by shfl to lane 0,
// which holds the cell state in a register and writes h. Sync protocol is the
// proven R3/R7 counter barrier (coalesced-ish publish -> sync -> release+spin).
__global__ __launch_bounds__(256, 1) void lstm_persistent(
    const float* __restrict__ Whh,      // [4096][1024]
    const float* __restrict__ gin_all,  // [50][4096]
    const float* __restrict__ c0) {     // [1024]
    const int b = blockIdx.x;
    const int tid = threadIdx.x;
    const int w = tid >> 5;              // warp -> unit b*8+w
    const int lane = tid & 31;
    const int r = lane >> 3;             // gate 0..3
    const int c = lane & 7;              // chunk 0..7
    const int u = b * 8 + w;
    const int grow = r * 1024 + u;       // W_hh row for this lane

    __shared__ __align__(16) ull h_q[512];  // h packed as f32x2 pairs
    __shared__ float sGin[NSTEP][4][8];     // this block's Gin slice, all steps

    // preload Gin slice (off the per-step chain)
    if (tid < 200) {
        int t = tid >> 2, g = tid & 3;
        const float4* src = (const float4*)(gin_all + (size_t)t * 4096 + g * 1024 + b * 8);
        ((float4*)&sGin[t][g][0])[0] = src[0];
        ((float4*)&sGin[t][g][0])[1] = src[1];
    }
    float cc = 0.f;
    if (lane == 0) cc = c0[u];

    // W_hh slice into registers, pre-packed as f32x2 pairs
    ull Wq[64];
    const float4* wp = (const float4*)(Whh + (size_t)grow * 1024);
#pragma unroll
    for (int it = 0; it < 32; it++) {
        float4 w4 = wp[it * 8 + c];
        Wq[2 * it + 0] = pack2(w4.x, w4.y);
        Wq[2 * it + 1] = pack2(w4.z, w4.w);
    }
    __syncthreads();

    for (int t = 0; t < NSTEP; t++) {
        // stage h packed (prior barrier guarantees visibility)
        {
            float4 hv = ((const float4*)g_h[t & 1])[tid];
            ulonglong2 hq;
            hq.x = pack2(hv.x, hv.y);
            hq.y = pack2(hv.z, hv.w);
            *((ulonglong2*)&h_q[2 * tid]) = hq;
        }
        __syncthreads();

        ull a0 = 0, a1 = 0;
#pragma unroll
        for (int it = 0; it < 32; it++) {
            ulonglong2 hq = *(const ulonglong2*)&h_q[it * 16 + c * 2];  // bcast, conflict-free
            ffma2(a0, Wq[2 * it + 0], hq.x);
            ffma2(a1, Wq[2 * it + 1], hq.y);
        }
        float sum = sum2(a0) + sum2(a1);
        // reduce over the 8 chunk lanes (within each gate's lane group)
        sum += __shfl_xor_sync(0xFFFFFFFFu, sum, 1);
        sum += __shfl_xor_sync(0xFFFFFFFFu, sum, 2);
        sum += __shfl_xor_sync(0xFFFFFFFFu, sum, 4);
        sum += sGin[t][r][w];  // add input projection + biases

        // gather the 4 gate values to lane 0
        float vi = __shfl_sync(0xFFFFFFFFu, sum, 0);
        float vf = __shfl_sync(0xFFFFFFFFu, sum, 8);
        float vg = __shfl_sync(0xFFFFFFFFu, sum, 16);
        float vo = __shfl_sync(0xFFFFFFFFu, sum, 24);

        if (lane == 0) {
            float ig = __fdividef(1.f, 1.f + __expf(-vi));
            float fg = __fdividef(1.f, 1.f + __expf(-vf));
            float gg = 1.f - __fdividef(2.f, __expf(2.f * vg) + 1.f);
            float og = __fdividef(1.f, 1.f + __expf(-vo));
            float cn = fg * cc + ig * gg;
            cc = cn;
            float hn = og * (1.f - __fdividef(2.f, __expf(2.f * cn) + 1.f));
            g_h[(t + 1) & 1][u] = hn;          // 8 adjacent words per block
            g_HS[(size_t)t * 1024 + u] = hn;
        }
        __syncthreads();  // all warps' stores ordered before the release

        if (tid == 0) {
            red_release_add1(&g_arrive);  // release publishes block's writes
            const unsigned target = (unsigned)NBLK * (unsigned)(t + 1);
            while (ld_acquire(&g_arrive) < target) {}
        }
        __syncthreads();
    }
}

// ---------------- launch ----------------
extern "C" void kernel_launch(void* const* d_in, const int* in_sizes, int n_in,
                              void* d_out, int out_size) {
    const int* sent = (const int*)d_in[0];
    const float* h0 = (const float*)d_in[1];
    const float* c0 = (const float*)d_in[2];
    const float* emb = (const float*)d_in[3];
    const float* Wih = (const float*)d_in[4];
    const float* Whh = (const float*)d_in[5];
    const float* bih = (const float*)d_in[6];
    const float* bhh = (const float*)d_in[7];
    const float* Wout = (const float*)d_in[8];
    const float* bout = (const float*)d_in[9];
    float* out = (float*)d_out;

    float* gX;
    float* gGin;
    float* gHS;
    float* gP;
    cudaGetSymbolAddress((void**)&gX, g_X);
    cudaGetSymbolAddress((void**)&gGin, g_Gin);
    cudaGetSymbolAddress((void**)&gHS, g_HS);
    cudaGetSymbolAddress((void**)&gP, g_P);

    // 1) gather inputs + init state + reset barrier
    prep_kernel<<<65, 256>>>(sent, emb, h0);

    // 2) input projection, split-K=8: partials then combine (+ biases)
    {
        dim3 grid(4096 / 128, SPLITK_IN);
        gemm_splitk<<<grid, 128>>>(gX, Wih, gP, 4096, 1024, 4096, SPLITK_IN);
        dim3 cgrid(4096 / 256, 50);
        combine_gin_kernel<<<cgrid, 256>>>(bih, bhh);
    }

    // 3) persistent recurrence (register-resident W_hh, counter barrier)
    lstm_persistent<<<NBLK, 256>>>(Whh, gGin, c0);

    // 4) output projection, split-K=4: partials then combine (+ bias)
    {
        dim3 grid(LDP_OUT / 128, SPLITK_OUT);
        gemm_splitk<<<grid, 128>>>(gHS, Wout, gP, NOUT, 1024, LDP_OUT, SPLITK_OUT);
        dim3 cgrid((NOUT + 255) / 256, 50);
        combine_out_kernel<<<cgrid, 256>>>(bout, out);
    }
}

// round 10
// speedup vs baseline: 1.1381x; 1.1381x over previous
#include <cuda_runtime.h>
#include <cuda_bf16.h>
#include <math.h>
#include <stdint.h>

typedef unsigned long long ull;

#define NBLK 128
#define NSTEP 50
#define NOUT 50257

// ---------------- device scratch (no allocs allowed) ----------------
__device__ float g_X[64 * 1024];      // padded inputs (rows 50..63 zero)
__device__ float g_Gin[50 * 4096];    // W_ih @ x_t + b_ih + b_hh
__device__ float g_HS[64 * 1024];     // h_t history (rows 50..63 zero)
__device__ float g_h[2][1024];        // double-buffered hidden state
__device__ unsigned g_arrive;         // cumulative grid-barrier counter

// ---------------- helpers ----------------
__device__ __forceinline__ ull pack2(float x, float y) {
    ull r;
    asm("mov.b64 %0, {%1, %2};" : "=l"(r) : "f"(x), "f"(y));
    return r;
}
__device__ __forceinline__ void ffma2(ull& d, ull a, ull b) {
    asm("fma.rn.f32x2 %0, %1, %2, %0;" : "+l"(d) : "l"(a), "l"(b));
}
__device__ __forceinline__ float sum2(ull a) {
    float2 v = *(float2*)&a;
    return v.x + v.y;
}
__device__ __forceinline__ void red_release_add1(unsigned* p) {
    asm volatile("red.release.gpu.global.add.u32 [%0], 1;" :: "l"(p) : "memory");
}
__device__ __forceinline__ unsigned ld_acquire(const unsigned* p) {
    unsigned v;
    asm volatile("ld.acquire.gpu.global.u32 %0, [%1];" : "=r"(v) : "l"(p) : "memory");
    return v;
}

// bf16 hi/lo split of a float pair, packed little-endian (x=low half)
__device__ __forceinline__ void cvt_pair(float x, float y, unsigned& hi, unsigned& lo) {
    __nv_bfloat162 h = __floats2bfloat162_rn(x, y);
    float rx = x - __bfloat162float(h.x);
    float ry = y - __bfloat162float(h.y);
    __nv_bfloat162 l = __floats2bfloat162_rn(rx, ry);
    hi = *(unsigned*)&h;
    lo = *(unsigned*)&l;
}

// mma.sync m16n8k16 bf16 (baseline PTX, works on compute_100)
__device__ __forceinline__ void mma_bf16(float* d, const unsigned* a, const unsigned* b) {
    asm volatile(
        "mma.sync.aligned.m16n8k16.row.col.f32.bf16.bf16.f32 "
        "{%0,%1,%2,%3}, {%4,%5,%6,%7}, {%8,%9}, {%0,%1,%2,%3};"
        : "+f"(d[0]), "+f"(d[1]), "+f"(d[2]), "+f"(d[3])
        : "r"(a[0]), "r"(a[1]), "r"(a[2]), "r"(a[3]), "r"(b[0]), "r"(b[1]));
}

// ---------------- prep: gather X rows, zero pads, init state, reset barrier ----------------
__global__ void prep_kernel(const int* __restrict__ sent,
                            const float* __restrict__ emb,
                            const float* __restrict__ h0) {
    int b = blockIdx.x;
    int tid = threadIdx.x;  // 256 threads, float4 each -> 1024 floats
    if (b < 64) {
        float4* dst = (float4*)(g_X + (size_t)b * 1024);
        if (b < 50) {
            int row = (b == 0) ? 1 : sent[b - 1];  // START_ID = 1
            const float4* src = (const float4*)(emb + (size_t)row * 1024);
            dst[tid] = src[tid];
        } else {
            float4 z = make_float4(0.f, 0.f, 0.f, 0.f);
            dst[tid] = z;
            ((float4*)(g_HS + (size_t)b * 1024))[tid] = z;  // zero MMA pad rows
        }
    } else {
        ((float4*)g_h[0])[tid] = ((const float4*)h0)[tid];
        if (tid == 0) g_arrive = 0u;
    }
}

// ---------------- bf16x3 tensor-core GEMM: C[m][n] = A[m][:]·W[n][:] + bias ----------------
// A: [64][K] fp32 (rows >=50 zero). W: [N][K] fp32 row-major. K = 1024.
// CTA: BM=64, BN=64, 4 warps; warp = full M x 16 N (2 n8 tiles); BK=16 steps.
// 3-term bf16 split per step: D += Ah*Bh + Ah*Bl + Al*Bh.
__global__ __launch_bounds__(128) void gemm_bf16x3(
    const float* __restrict__ A, const float* __restrict__ W,
    float* __restrict__ C,
    const float* __restrict__ bias1, const float* __restrict__ bias2,
    int N, int ldc) {
    // padded stride 9 b32 (18 bf16) to spread banks
    __shared__ unsigned sAh[64][9];
    __shared__ unsigned sAl[64][9];
    __shared__ unsigned sBh[64][9];
    __shared__ unsigned sBl[64][9];

    const int tid = threadIdx.x;
    const int wid = tid >> 5;
    const int lane = tid & 31;
    const int l4 = lane >> 2;   // group 0..7
    const int lq = lane & 3;    // thread-in-group
    const int n_block = blockIdx.x * 64;

    float d[4][2][4];
#pragma unroll
    for (int mt = 0; mt < 4; mt++)
#pragma unroll
        for (int nt = 0; nt < 2; nt++)
#pragma unroll
            for (int q = 0; q < 4; q++) d[mt][nt][q] = 0.f;

    // global-load mapping: 128 threads x 2 float4 cover one 64x16 fp32 tile
    // f4 index i: row = i>>2, quarter q=i&3 -> cols k0+q*4..+3
    for (int kt = 0; kt < 64; kt++) {
        const int k0 = kt * 16;
        __syncthreads();  // previous step's mma done before overwrite
#pragma unroll
        for (int s = 0; s < 2; s++) {
            int i = s * 128 + tid;
            int row = i >> 2;
            int q = i & 3;
            // A tile
            {
                float4 v = *(const float4*)(A + (size_t)row * 1024 + k0 + q * 4);
                unsigned h0, l0, h1, l1;
                cvt_pair(v.x, v.y, h0, l0);
                cvt_pair(v.z, v.w, h1, l1);
                sAh[row][q * 2] = h0;
                sAh[row][q * 2 + 1] = h1;
                sAl[row][q * 2] = l0;
                sAl[row][q * 2 + 1] = l1;
            }
            // B tile (guard N tail)
            {
                int gn = n_block + row;
                float4 v = make_float4(0.f, 0.f, 0.f, 0.f);
                if (gn < N) v = *(const float4*)(W + (size_t)gn * 1024 + k0 + q * 4);
                unsigned h0, l0, h1, l1;
                cvt_pair(v.x, v.y, h0, l0);
                cvt_pair(v.z, v.w, h1, l1);
                sBh[row][q * 2] = h0;
                sBh[row][q * 2 + 1] = h1;
                sBl[row][q * 2] = l0;
                sBl[row][q * 2 + 1] = l1;
            }
        }
        __syncthreads();

        // B fragments for this warp's two n8 tiles
        unsigned bh[2][2], bl[2][2];
#pragma unroll
        for (int nt = 0; nt < 2; nt++) {
            int n = wid * 16 + nt * 8 + l4;
            bh[nt][0] = sBh[n][lq];
            bh[nt][1] = sBh[n][lq + 4];
            bl[nt][0] = sBl[n][lq];
            bl[nt][1] = sBl[n][lq + 4];
        }
#pragma unroll
        for (int mt = 0; mt < 4; mt++) {
            int r0 = mt * 16 + l4;
            unsigned ah[4], al[4];
            ah[0] = sAh[r0][lq];
            ah[1] = sAh[r0 + 8][lq];
            ah[2] = sAh[r0][lq + 4];
            ah[3] = sAh[r0 + 8][lq + 4];
            al[0] = sAl[r0][lq];
            al[1] = sAl[r0 + 8][lq];
            al[2] = sAl[r0][lq + 4];
            al[3] = sAl[r0 + 8][lq + 4];
#pragma unroll
            for (int nt = 0; nt < 2; nt++) {
                mma_bf16(d[mt][nt], ah, bh[nt]);
                mma_bf16(d[mt][nt], ah, bl[nt]);
                mma_bf16(d[mt][nt], al, bh[nt]);
            }
        }
    }

    // epilogue: d[mt][nt] -> rows m<50, cols<N, + bias
#pragma unroll
    for (int mt = 0; mt < 4; mt++) {
        int row0 = mt * 16 + l4;
#pragma unroll
        for (int nt = 0; nt < 2; nt++) {
            int col0 = n_block + wid * 16 + nt * 8 + lq * 2;
#pragma unroll
            for (int half = 0; half < 2; half++) {
                int row = row0 + half * 8;
                if (row < 50) {
                    float* crow = C + (size_t)row * ldc;
                    if (col0 < N) {
                        float bv = bias1[col0] + (bias2 ? bias2[col0] : 0.f);
                        crow[col0] = d[mt][nt][half * 2 + 0] + bv;
                    }
                    if (col0 + 1 < N) {
                        float bv = bias1[col0 + 1] + (bias2 ? bias2[col0 + 1] : 0.f);
                        crow[col0 + 1] = d[mt][nt][half * 2 + 1] + bv;
                    }
                }
            }
        }
    }
}

// ---------------- persistent LSTM (R8-proven, unchanged) ----------------
__global__ __launch_bounds__(256, 1) void lstm_persistent(
    const float* __restrict__ Whh,      // [4096][1024]
    const float* __restrict__ gin_all,  // [50][4096]
    const float* __restrict__ c0) {     // [1024]
    const int b = blockIdx.x;
    const int tid = threadIdx.x;
    const int w = tid >> 5;              // warp -> unit b*8+w
    const int lane = tid & 31;
    const int r = lane >> 3;             // gate 0..3
    const int c = lane & 7;              // chunk 0..7
    const int u = b * 8 + w;
    const int grow = r * 1024 + u;

    __shared__ __align__(16) ull h_q[512];
    __shared__ float sGin[NSTEP][4][8];

    if (tid < 200) {
        int t = tid >> 2, g = tid & 3;
        const float4* src = (const float4*)(gin_all + (size_t)t * 4096 + g * 1024 + b * 8);
        ((float4*)&sGin[t][g][0])[0] = src[0];
        ((float4*)&sGin[t][g][0])[1] = src[1];
    }
    float cc = 0.f;
    if (lane == 0) cc = c0[u];

    ull Wq[64];
    const float4* wp = (const float4*)(Whh + (size_t)grow * 1024);
#pragma unroll
    for (int it = 0; it < 32; it++) {
        float4 w4 = wp[it * 8 + c];
        Wq[2 * it + 0] = pack2(w4.x, w4.y);
        Wq[2 * it + 1] = pack2(w4.z, w4.w);
    }
    __syncthreads();

    for (int t = 0; t < NSTEP; t++) {
        {
            float4 hv = ((const float4*)g_h[t & 1])[tid];
            ulonglong2 hq;
            hq.x = pack2(hv.x, hv.y);
            hq.y = pack2(hv.z, hv.w);
            *((ulonglong2*)&h_q[2 * tid]) = hq;
        }
        __syncthreads();

        ull a0 = 0, a1 = 0;
#pragma unroll
        for (int it = 0; it < 32; it++) {
            ulonglong2 hq = *(const ulonglong2*)&h_q[it * 16 + c * 2];
            ffma2(a0, Wq[2 * it + 0], hq.x);
            ffma2(a1, Wq[2 * it + 1], hq.y);
        }
        float sum = sum2(a0) + sum2(a1);
        sum += __shfl_xor_sync(0xFFFFFFFFu, sum, 1);
        sum += __shfl_xor_sync(0xFFFFFFFFu, sum, 2);
        sum += __shfl_xor_sync(0xFFFFFFFFu, sum, 4);
        sum += sGin[t][r][w];

        float vi = __shfl_sync(0xFFFFFFFFu, sum, 0);
        float vf = __shfl_sync(0xFFFFFFFFu, sum, 8);
        float vg = __shfl_sync(0xFFFFFFFFu, sum, 16);
        float vo = __shfl_sync(0xFFFFFFFFu, sum, 24);

        if (lane == 0) {
            float ig = __fdividef(1.f, 1.f + __expf(-vi));
            float fg = __fdividef(1.f, 1.f + __expf(-vf));
            float gg = 1.f - __fdividef(2.f, __expf(2.f * vg) + 1.f);
            float og = __fdividef(1.f, 1.f + __expf(-vo));
            float cn = fg * cc + ig * gg;
            cc = cn;
            float hn = og * (1.f - __fdividef(2.f, __expf(2.f * cn) + 1.f));
            g_h[(t + 1) & 1][u] = hn;
            g_HS[(size_t)t * 1024 + u] = hn;
        }
        __syncthreads();

        if (tid == 0) {
            red_release_add1(&g_arrive);
            const unsigned target = (unsigned)NBLK * (unsigned)(t + 1);
            while (ld_acquire(&g_arrive) < target) {}
        }
        __syncthreads();
    }
}

// ---------------- launch ----------------
extern "C" void kernel_launch(void* const* d_in, const int* in_sizes, int n_in,
                              void* d_out, int out_size) {
    const int* sent = (const int*)d_in[0];
    const float* h0 = (const float*)d_in[1];
    const float* c0 = (const float*)d_in[2];
    const float* emb = (const float*)d_in[3];
    const float* Wih = (const float*)d_in[4];
    const float* Whh = (const float*)d_in[5];
    const float* bih = (const float*)d_in[6];
    const float* bhh = (const float*)d_in[7];
    const float* Wout = (const float*)d_in[8];
    const float* bout = (const float*)d_in[9];
    float* out = (float*)d_out;

    float* gX;
    float* gGin;
    float* gHS;
    cudaGetSymbolAddress((void**)&gX, g_X);
    cudaGetSymbolAddress((void**)&gGin, g_Gin);
    cudaGetSymbolAddress((void**)&gHS, g_HS);

    // 1) gather inputs + init state + reset barrier
    prep_kernel<<<65, 256>>>(sent, emb, h0);

    // 2) input projection: Gin = X @ W_ih^T + (b_ih + b_hh)   [bf16x3 mma]
    gemm_bf16x3<<<4096 / 64, 128>>>(gX, Wih, gGin, bih, bhh, 4096, 4096);

    // 3) persistent recurrence (register-resident W_hh, counter barrier)
    lstm_persistent<<<NBLK, 256>>>(Whh, gGin, c0);

    // 4) output projection: logits = HS @ W_out^T + b_out     [bf16x3 mma]
    gemm_bf16x3<<<(NOUT + 63) / 64, 128>>>(gHS, Wout, out, bout, nullptr,
                                           NOUT, NOUT);
}

// round 11
// speedup vs baseline: 1.5846x; 1.3923x over previous
#include <cuda_runtime.h>
#include <cuda_bf16.h>
#include <math.h>
#include <stdint.h>

typedef unsigned long long ull;

#define NBLK 128
#define NSTEP 50
#define NOUT 50257

// ---------------- device scratch (no allocs allowed) ----------------
__device__ float g_X[64 * 1024];      // padded inputs (rows 50..63 zero)
__device__ float g_Gin[50 * 4096];    // W_ih @ x_t + b_ih + b_hh
__device__ float g_HS[64 * 1024];     // h_t history (rows 50..63 zero)
__device__ float g_h[2][1024];        // double-buffered hidden state
__device__ unsigned g_arrive;         // cumulative grid-barrier counter
__device__ __align__(16) unsigned g_Ah[64 * 512];  // A bf16-hi pairs (X or HS)
__device__ __align__(16) unsigned g_Al[64 * 512];  // A bf16-lo pairs

// ---------------- helpers ----------------
__device__ __forceinline__ ull pack2(float x, float y) {
    ull r;
    asm("mov.b64 %0, {%1, %2};" : "=l"(r) : "f"(x), "f"(y));
    return r;
}
__device__ __forceinline__ void ffma2(ull& d, ull a, ull b) {
    asm("fma.rn.f32x2 %0, %1, %2, %0;" : "+l"(d) : "l"(a), "l"(b));
}
__device__ __forceinline__ float sum2(ull a) {
    float2 v = *(float2*)&a;
    return v.x + v.y;
}
__device__ __forceinline__ void red_release_add1(unsigned* p) {
    asm volatile("red.release.gpu.global.add.u32 [%0], 1;" :: "l"(p) : "memory");
}
__device__ __forceinline__ unsigned ld_acquire(const unsigned* p) {
    unsigned v;
    asm volatile("ld.acquire.gpu.global.u32 %0, [%1];" : "=r"(v) : "l"(p) : "memory");
    return v;
}

// bf16 hi/lo split of a float pair, packed little-endian (x=low half)
__device__ __forceinline__ void cvt_pair(float x, float y, unsigned& hi, unsigned& lo) {
    __nv_bfloat162 h = __floats2bfloat162_rn(x, y);
    float rx = x - __bfloat162float(h.x);
    float ry = y - __bfloat162float(h.y);
    __nv_bfloat162 l = __floats2bfloat162_rn(rx, ry);
    hi = *(unsigned*)&h;
    lo = *(unsigned*)&l;
}

// mma.sync m16n8k16 bf16 (baseline PTX, works on compute_100)
__device__ __forceinline__ void mma_bf16(float* d, const unsigned* a, const unsigned* b) {
    asm volatile(
        "mma.sync.aligned.m16n8k16.row.col.f32.bf16.bf16.f32 "
        "{%0,%1,%2,%3}, {%4,%5,%6,%7}, {%8,%9}, {%0,%1,%2,%3};"
        : "+f"(d[0]), "+f"(d[1]), "+f"(d[2]), "+f"(d[3])
        : "r"(a[0]), "r"(a[1]), "r"(a[2]), "r"(a[3]), "r"(b[0]), "r"(b[1]));
}

// ---------------- prep: gather X rows, zero pads, init state, reset barrier ----------------
__global__ void prep_kernel(const int* __restrict__ sent,
                            const float* __restrict__ emb,
                            const float* __restrict__ h0) {
    int b = blockIdx.x;
    int tid = threadIdx.x;  // 256 threads, float4 each -> 1024 floats
    if (b < 64) {
        float4* dst = (float4*)(g_X + (size_t)b * 1024);
        if (b < 50) {
            int row = (b == 0) ? 1 : sent[b - 1];  // START_ID = 1
            const float4* src = (const float4*)(emb + (size_t)row * 1024);
            dst[tid] = src[tid];
        } else {
            float4 z = make_float4(0.f, 0.f, 0.f, 0.f);
            dst[tid] = z;
            ((float4*)(g_HS + (size_t)b * 1024))[tid] = z;  // zero MMA pad rows
        }
    } else {
        ((float4*)g_h[0])[tid] = ((const float4*)h0)[tid];
        if (tid == 0) g_arrive = 0u;
    }
}

// ---------------- split a fp32 [64][1024] matrix into packed bf16 hi/lo ----------------
__global__ void cvt_split_kernel(const float* __restrict__ src) {
    int i = blockIdx.x * 256 + threadIdx.x;  // over 32768 float2 pairs
    float2 v = ((const float2*)src)[i];
    unsigned hi, lo;
    cvt_pair(v.x, v.y, hi, lo);
    g_Ah[i] = hi;
    g_Al[i] = lo;
}

// ---------------- bf16x3 tensor-core GEMM: C[m][n] = A[m][:]·W[n][:] + bias ----------------
// A: precomputed hi/lo packed bf16 pairs [64][512]. W: [N][1024] fp32 row-major.
// CTA: BM=64, BN=NT*32, 4 warps; warp = full M x NT*8 N. BK=16 steps, K=1024.
// 3-term bf16 split: D += Ah*Bh + Ah*Bl + Al*Bh.
template <int NT>
__global__ __launch_bounds__(128) void gemm_bf16x3(
    const unsigned* __restrict__ Ah, const unsigned* __restrict__ Al,
    const float* __restrict__ W, float* __restrict__ C,
    const float* __restrict__ bias1, const float* __restrict__ bias2,
    int N, int ldc) {
    constexpr int BN = NT * 32;
    // pad 12 words keeps uint4 STS 16B-aligned; frag LDS banks (12r+q)%32 conflict-free
    __shared__ unsigned sAh[64][12];
    __shared__ unsigned sAl[64][12];
    __shared__ unsigned sBh[BN][12];
    __shared__ unsigned sBl[BN][12];

    const int tid = threadIdx.x;
    const int wid = tid >> 5;
    const int lane = tid & 31;
    const int l4 = lane >> 2;   // group 0..7
    const int lq = lane & 3;    // thread-in-group
    const int n_block = blockIdx.x * BN;

    float d[4][NT][4];
#pragma unroll
    for (int mt = 0; mt < 4; mt++)
#pragma unroll
        for (int nt = 0; nt < NT; nt++)
#pragma unroll
            for (int q = 0; q < 4; q++) d[mt][nt][q] = 0.f;

    // fill mappings
    const int ar = tid >> 1;              // A row 0..63
    const int aseg = (tid & 1) * 4;       // word segment {0,4}

    // prologue: prefetch kt=0
    uint4 pah = *(const uint4*)(Ah + (size_t)ar * 512 + aseg);
    uint4 pal = *(const uint4*)(Al + (size_t)ar * 512 + aseg);
    float4 pb[NT];
#pragma unroll
    for (int s = 0; s < NT; s++) {
        int i = s * 128 + tid;
        int row = i >> 2, q = i & 3;
        int gn = n_block + row;
        pb[s] = make_float4(0.f, 0.f, 0.f, 0.f);
        if (gn < N) pb[s] = *(const float4*)(W + (size_t)gn * 1024 + q * 4);
    }

    for (int kt = 0; kt < 64; kt++) {
        // ---- STS current tile from prefetch registers ----
        *(uint4*)&sAh[ar][aseg] = pah;
        *(uint4*)&sAl[ar][aseg] = pal;
#pragma unroll
        for (int s = 0; s < NT; s++) {
            int i = s * 128 + tid;
            int row = i >> 2, q = i & 3;
            unsigned h0, l0, h1, l1;
            cvt_pair(pb[s].x, pb[s].y, h0, l0);
            cvt_pair(pb[s].z, pb[s].w, h1, l1);
            sBh[row][q * 2] = h0;
            sBh[row][q * 2 + 1] = h1;
            sBl[row][q * 2] = l0;
            sBl[row][q * 2 + 1] = l1;
        }
        __syncthreads();

        // ---- prefetch next tile (latency hidden under mma) ----
        if (kt + 1 < 64) {
            const int kp = (kt + 1) * 16;
            pah = *(const uint4*)(Ah + (size_t)ar * 512 + (kt + 1) * 8 + aseg);
            pal = *(const uint4*)(Al + (size_t)ar * 512 + (kt + 1) * 8 + aseg);
#pragma unroll
            for (int s = 0; s < NT; s++) {
                int i = s * 128 + tid;
                int row = i >> 2, q = i & 3;
                int gn = n_block + row;
                pb[s] = make_float4(0.f, 0.f, 0.f, 0.f);
                if (gn < N) pb[s] = *(const float4*)(W + (size_t)gn * 1024 + kp + q * 4);
            }
        }

        // ---- fragments + mma ----
        unsigned bh[NT][2], bl[NT][2];
#pragma unroll
        for (int nt = 0; nt < NT; nt++) {
            int n = wid * (NT * 8) + nt * 8 + l4;
            bh[nt][0] = sBh[n][lq];
            bh[nt][1] = sBh[n][lq + 4];
            bl[nt][0] = sBl[n][lq];
            bl[nt][1] = sBl[n][lq + 4];
        }
#pragma unroll
        for (int mt = 0; mt < 4; mt++) {
            int r0 = mt * 16 + l4;
            unsigned ah[4], al[4];
            ah[0] = sAh[r0][lq];
            ah[1] = sAh[r0 + 8][lq];
            ah[2] = sAh[r0][lq + 4];
            ah[3] = sAh[r0 + 8][lq + 4];
            al[0] = sAl[r0][lq];
            al[1] = sAl[r0 + 8][lq];
            al[2] = sAl[r0][lq + 4];
            al[3] = sAl[r0 + 8][lq + 4];
#pragma unroll
            for (int nt = 0; nt < NT; nt++) {
                mma_bf16(d[mt][nt], ah, bh[nt]);
                mma_bf16(d[mt][nt], ah, bl[nt]);
                mma_bf16(d[mt][nt], al, bh[nt]);
            }
        }
        __syncthreads();
    }

    // epilogue: d[mt][nt] -> rows m<50, cols<N, + bias
#pragma unroll
    for (int mt = 0; mt < 4; mt++) {
        int row0 = mt * 16 + l4;
#pragma unroll
        for (int nt = 0; nt < NT; nt++) {
            int col0 = n_block + wid * (NT * 8) + nt * 8 + lq * 2;
#pragma unroll
            for (int half = 0; half < 2; half++) {
                int row = row0 + half * 8;
                if (row < 50) {
                    float* crow = C + (size_t)row * ldc;
                    if (col0 < N) {
                        float bv = bias1[col0] + (bias2 ? bias2[col0] : 0.f);
                        crow[col0] = d[mt][nt][half * 2 + 0] + bv;
                    }
                    if (col0 + 1 < N) {
                        float bv = bias1[col0 + 1] + (bias2 ? bias2[col0 + 1] : 0.f);
                        crow[col0 + 1] = d[mt][nt][half * 2 + 1] + bv;
                    }
                }
            }
        }
    }
}

// ---------------- persistent LSTM (R8-proven, unchanged) ----------------
__global__ __launch_bounds__(256, 1) void lstm_persistent(
    const float* __restrict__ Whh,      // [4096][1024]
    const float* __restrict__ gin_all,  // [50][4096]
    const float* __restrict__ c0) {     // [1024]
    const int b = blockIdx.x;
    const int tid = threadIdx.x;
    const int w = tid >> 5;              // warp -> unit b*8+w
    const int lane = tid & 31;
    const int r = lane >> 3;             // gate 0..3
    const int c = lane & 7;              // chunk 0..7
    const int u = b * 8 + w;
    const int grow = r * 1024 + u;

    __shared__ __align__(16) ull h_q[512];
    __shared__ float sGin[NSTEP][4][8];

    if (tid < 200) {
        int t = tid >> 2, g = tid & 3;
        const float4* src = (const float4*)(gin_all + (size_t)t * 4096 + g * 1024 + b * 8);
        ((float4*)&sGin[t][g][0])[0] = src[0];
        ((float4*)&sGin[t][g][0])[1] = src[1];
    }
    float cc = 0.f;
    if (lane == 0) cc = c0[u];

    ull Wq[64];
    const float4* wp = (const float4*)(Whh + (size_t)grow * 1024);
#pragma unroll
    for (int it = 0; it < 32; it++) {
        float4 w4 = wp[it * 8 + c];
        Wq[2 * it + 0] = pack2(w4.x, w4.y);
        Wq[2 * it + 1] = pack2(w4.z, w4.w);
    }
    __syncthreads();

    for (int t = 0; t < NSTEP; t++) {
        {
            float4 hv = ((const float4*)g_h[t & 1])[tid];
            ulonglong2 hq;
            hq.x = pack2(hv.x, hv.y);
            hq.y = pack2(hv.z, hv.w);
            *((ulonglong2*)&h_q[2 * tid]) = hq;
        }
        __syncthreads();

        ull a0 = 0, a1 = 0;
#pragma unroll
        for (int it = 0; it < 32; it++) {
            ulonglong2 hq = *(const ulonglong2*)&h_q[it * 16 + c * 2];
            ffma2(a0, Wq[2 * it + 0], hq.x);
            ffma2(a1, Wq[2 * it + 1], hq.y);
        }
        float sum = sum2(a0) + sum2(a1);
        sum += __shfl_xor_sync(0xFFFFFFFFu, sum, 1);
        sum += __shfl_xor_sync(0xFFFFFFFFu, sum, 2);
        sum += __shfl_xor_sync(0xFFFFFFFFu, sum, 4);
        sum += sGin[t][r][w];

        float vi = __shfl_sync(0xFFFFFFFFu, sum, 0);
        float vf = __shfl_sync(0xFFFFFFFFu, sum, 8);
        float vg = __shfl_sync(0xFFFFFFFFu, sum, 16);
        float vo = __shfl_sync(0xFFFFFFFFu, sum, 24);

        if (lane == 0) {
            float ig = __fdividef(1.f, 1.f + __expf(-vi));
            float fg = __fdividef(1.f, 1.f + __expf(-vf));
            float gg = 1.f - __fdividef(2.f, __expf(2.f * vg) + 1.f);
            float og = __fdividef(1.f, 1.f + __expf(-vo));
            float cn = fg * cc + ig * gg;
            cc = cn;
            float hn = og * (1.f - __fdividef(2.f, __expf(2.f * cn) + 1.f));
            g_h[(t + 1) & 1][u] = hn;
            g_HS[(size_t)t * 1024 + u] = hn;
        }
        __syncthreads();

        if (tid == 0) {
            red_release_add1(&g_arrive);
            const unsigned target = (unsigned)NBLK * (unsigned)(t + 1);
            while (ld_acquire(&g_arrive) < target) {}
        }
        __syncthreads();
    }
}

// ---------------- launch ----------------
extern "C" void kernel_launch(void* const* d_in, const int* in_sizes, int n_in,
                              void* d_out, int out_size) {
    const int* sent = (const int*)d_in[0];
    const float* h0 = (const float*)d_in[1];
    const float* c0 = (const float*)d_in[2];
    const float* emb = (const float*)d_in[3];
    const float* Wih = (const float*)d_in[4];
    const float* Whh = (const float*)d_in[5];
    const float* bih = (const float*)d_in[6];
    const float* bhh = (const float*)d_in[7];
    const float* Wout = (const float*)d_in[8];
    const float* bout = (const float*)d_in[9];
    float* out = (float*)d_out;

    float* gX;
    float* gGin;
    float* gHS;
    unsigned* gAh;
    unsigned* gAl;
    cudaGetSymbolAddress((void**)&gX, g_X);
    cudaGetSymbolAddress((void**)&gGin, g_Gin);
    cudaGetSymbolAddress((void**)&gHS, g_HS);
    cudaGetSymbolAddress((void**)&gAh, g_Ah);
    cudaGetSymbolAddress((void**)&gAl, g_Al);

    // 1) gather inputs + init state + reset barrier
    prep_kernel<<<65, 256>>>(sent, emb, h0);

    // 2) input projection: Gin = X @ W_ih^T + (b_ih + b_hh)
    cvt_split_kernel<<<128, 256>>>(gX);
    gemm_bf16x3<2><<<4096 / 64, 128>>>(gAh, gAl, Wih, gGin, bih, bhh, 4096, 4096);

    // 3) persistent recurrence (register-resident W_hh, counter barrier)
    lstm_persistent<<<NBLK, 256>>>(Whh, gGin, c0);

    // 4) output projection: logits = HS @ W_out^T + b_out
    cvt_split_kernel<<<128, 256>>>(gHS);
    gemm_bf16x3<4><<<(NOUT + 127) / 128, 128>>>(gAh, gAl, Wout, out, bout, nullptr,
                                                NOUT, NOUT);
}